// round 5
// baseline (speedup 1.0000x reference)
#include <cuda_runtime.h>
#include <cstdint>

// ---------------- problem constants ----------------
static constexpr int BATCH    = 256;
static constexpr int NOUT     = 64;
static constexpr int KDIM     = 262144;          // 4*256*256
static constexpr int KTILE    = 32;              // fp32 per k-tile = 128 B
static constexpr int KT_TOTAL = KDIM / KTILE;    // 8192
static constexpr int NSPLIT   = 148;             // pure split-K, one CTA per SM

// padded smem layout: rows of 36 floats (32 data + 4 pad) -> conflict-free frag LDS
static constexpr int ROW_PAD      = 36;
static constexpr int A_ROWS       = 256;
static constexpr int B_ROWS       = 64;
static constexpr int A_BYTES      = A_ROWS * ROW_PAD * 4;   // 36864
static constexpr int B_BYTES      = B_ROWS * ROW_PAD * 4;   // 9216
static constexpr int STAGE_BYTES  = A_BYTES + B_BYTES;      // 46080
static constexpr int NSTAGE       = 4;
static constexpr int SMEM_BYTES   = NSTAGE * STAGE_BYTES;   // 184320

// ---------------- device scratch (no allocs allowed) ----------------
__device__ float g_Wp[(size_t)NOUT * KDIM];                  // 64 MB DWT-folded W (tf32-rounded)
__device__ float g_Part[(size_t)NSPLIT * BATCH * NOUT];      // 9.7 MB split-K partials

// ---------------- helpers ----------------
__device__ __forceinline__ uint32_t smem_u32(const void* p) {
    uint32_t a;
    asm("{ .reg .u64 t; cvta.to.shared.u64 t, %1; cvt.u32.u64 %0, t; }" : "=r"(a) : "l"(p));
    return a;
}
__device__ __forceinline__ float to_tf32_f(float f) {
    float r; asm("cvt.rna.tf32.f32 %0, %1;" : "=f"(r) : "f"(f)); return r;
}
__device__ __forceinline__ uint32_t f2tf(float f) {
    uint32_t r; asm("cvt.rna.tf32.f32 %0, %1;" : "=r"(r) : "f"(f)); return r;
}
__device__ __forceinline__ void cp_async16(uint32_t s, const void* g) {
    asm volatile("cp.async.cg.shared.global [%0], [%1], 16;" :: "r"(s), "l"(g));
}
__device__ __forceinline__ void cp_commit() {
    asm volatile("cp.async.commit_group;" ::: "memory");
}
__device__ __forceinline__ void cp_wait3() {
    asm volatile("cp.async.wait_group 3;" ::: "memory");
}
__device__ __forceinline__ void mma_tf32(float* c, const uint32_t* a, const uint32_t* b) {
    asm volatile(
        "mma.sync.aligned.m16n8k8.row.col.f32.tf32.tf32.f32 "
        "{%0,%1,%2,%3}, {%4,%5,%6,%7}, {%8,%9}, {%0,%1,%2,%3};"
        : "+f"(c[0]), "+f"(c[1]), "+f"(c[2]), "+f"(c[3])
        : "r"(a[0]), "r"(a[1]), "r"(a[2]), "r"(a[3]), "r"(b[0]), "r"(b[1]));
}

// ---------------- kernel 1: fold DWT adjoint into W -> Wp ----------------
// out = DWT(x) @ W.T = x @ Wp.T,  Wp[o; c, y=2i+r, xcol=2j+q] =
//   0.5*(u + s_q*v), u = W_LL + s_r*W_LH, v = W_HL + s_r*W_HH, s=+1(0)/-1(1)
__global__ __launch_bounds__(256)
void fold_w_kernel(const float* __restrict__ W) {
    int idx = blockIdx.x * 256 + threadIdx.x;     // 4,194,304 threads
    size_t base = (size_t)idx << 2;               // 4 consecutive Wp outputs
    int o    = (int)(base >> 18);
    int rem  = (int)(base & 262143);
    int c    = rem >> 16;
    int r2   = rem & 65535;
    int y    = r2 >> 8;
    int i    = y >> 1;
    int rpar = y & 1;
    int j0   = (r2 & 255) >> 1;                   // even j

    const float* wb = W + (size_t)o * KDIM + (size_t)c * 65536 + (size_t)i * 128;
    float w0a = __ldg(wb + j0),          w0b = __ldg(wb + j0 + 1);
    float w1a = __ldg(wb + 16384 + j0),  w1b = __ldg(wb + 16384 + j0 + 1);
    float w2a = __ldg(wb + 32768 + j0),  w2b = __ldg(wb + 32768 + j0 + 1);
    float w3a = __ldg(wb + 49152 + j0),  w3b = __ldg(wb + 49152 + j0 + 1);

    float sr = rpar ? -1.0f : 1.0f;
    float ua = fmaf(sr, w1a, w0a), va = fmaf(sr, w3a, w2a);
    float ub = fmaf(sr, w1b, w0b), vb = fmaf(sr, w3b, w2b);
    float4 outv;
    outv.x = to_tf32_f(0.5f * (ua + va));
    outv.y = to_tf32_f(0.5f * (ua - va));
    outv.z = to_tf32_f(0.5f * (ub + vb));
    outv.w = to_tf32_f(0.5f * (ub - vb));
    *reinterpret_cast<float4*>(g_Wp + base) = outv;
}

// ---------------- kernel 2: split-K tf32 mma.sync GEMM ----------------
// grid = 148 CTAs, each: full M=256, N=64, K tiles [t_begin, t_end)
// 8 warps = 4(M) x 2(N); warp tile 64x32; mma m16n8k8 tf32
__global__ __launch_bounds__(256, 1)
void gemm_tf32_kernel(const float* __restrict__ x) {
    extern __shared__ float smem[];
    const int tid  = threadIdx.x;
    const int lane = tid & 31;
    const int wid  = tid >> 5;
    const int wm   = wid >> 1;                    // 0..3 -> M offset wm*64
    const int wn   = wid & 1;                     // 0..1 -> N offset wn*32
    const int split = blockIdx.x;

    const int t_begin = (int)(((long)split * KT_TOTAL) / NSPLIT);
    const int t_end   = (int)(((long)(split + 1) * KT_TOTAL) / NSPLIT);
    const int nt      = t_end - t_begin;

    // producer mapping: per stage 2560 16B-chunks (A:2048, B:512), 10 per thread
    const int prow = tid >> 3;                    // 0..31
    const int pci  = tid & 7;
    const float* gA = x    + (size_t)prow * KDIM + (size_t)t_begin * KTILE + pci * 4;
    const float* gB = g_Wp + (size_t)prow * KDIM + (size_t)t_begin * KTILE + pci * 4;
    const uint32_t smem_b = smem_u32(smem);
    const uint32_t sA = smem_b + prow * (ROW_PAD * 4) + pci * 16;
    const uint32_t sB = smem_b + A_BYTES + prow * (ROW_PAD * 4) + pci * 16;

    auto issue_stage = [&](int s) {
        const uint32_t off = (uint32_t)(s & (NSTAGE - 1)) * STAGE_BYTES;
        const float* ga = gA + (size_t)s * KTILE;
        const float* gb = gB + (size_t)s * KTILE;
        #pragma unroll
        for (int u = 0; u < 8; ++u)               // A: rows prow + u*32 (256 rows)
            cp_async16(sA + off + u * (32 * ROW_PAD * 4), ga + (size_t)u * 32 * KDIM);
        #pragma unroll
        for (int v = 0; v < 2; ++v)               // B: rows prow + v*32 (64 rows)
            cp_async16(sB + off + v * (32 * ROW_PAD * 4), gb + (size_t)v * 32 * KDIM);
    };

    float acc[4][4][4];
    #pragma unroll
    for (int mt = 0; mt < 4; ++mt)
        #pragma unroll
        for (int nb = 0; nb < 4; ++nb)
            #pragma unroll
            for (int r = 0; r < 4; ++r) acc[mt][nb][r] = 0.0f;

    // prologue: 3 stages in flight
    issue_stage(0); cp_commit();
    issue_stage(1); cp_commit();
    issue_stage(2); cp_commit();

    const int g  = lane >> 2;                     // 0..7
    const int tg = lane & 3;                      // 0..3

    for (int t = 0; t < nt; ++t) {
        if (t + 3 < nt) issue_stage(t + 3);
        cp_commit();                              // always commit to keep group count aligned
        cp_wait3();                               // stage t complete (<=3 newer pending)
        __syncthreads();

        const float* As = smem + (size_t)(t & (NSTAGE - 1)) * (STAGE_BYTES / 4);
        const float* Bs = As + (A_BYTES / 4);

        #pragma unroll
        for (int ks = 0; ks < 4; ++ks) {          // 4 x K=8 per 32-float k-tile
            const int kc = ks * 8 + tg;
            uint32_t a[4][4], b[4][2];
            #pragma unroll
            for (int mt = 0; mt < 4; ++mt) {
                const float* ap = As + (size_t)(wm * 64 + mt * 16 + g) * ROW_PAD + kc;
                a[mt][0] = f2tf(ap[0]);
                a[mt][1] = f2tf(ap[8 * ROW_PAD]);
                a[mt][2] = f2tf(ap[4]);
                a[mt][3] = f2tf(ap[8 * ROW_PAD + 4]);
            }
            #pragma unroll
            for (int nb = 0; nb < 4; ++nb) {
                const float* bp = Bs + (size_t)(wn * 32 + nb * 8 + g) * ROW_PAD + kc;
                b[nb][0] = __float_as_uint(bp[0]);     // Wp already tf32-rounded
                b[nb][1] = __float_as_uint(bp[4]);
            }
            #pragma unroll
            for (int mt = 0; mt < 4; ++mt)
                #pragma unroll
                for (int nb = 0; nb < 4; ++nb)
                    mma_tf32(acc[mt][nb], a[mt], b[nb]);
        }
        __syncthreads();                          // buffer reuse guard
    }

    // epilogue: write 256x64 partial for this split
    float* pp = g_Part + (size_t)split * (BATCH * NOUT);
    const int r0 = wm * 64 + g;
    const int c0 = wn * 32 + tg * 2;
    #pragma unroll
    for (int mt = 0; mt < 4; ++mt) {
        #pragma unroll
        for (int nb = 0; nb < 4; ++nb) {
            const int rr = r0 + mt * 16;
            const int cc = c0 + nb * 8;
            float2 v01 = make_float2(acc[mt][nb][0], acc[mt][nb][1]);
            float2 v23 = make_float2(acc[mt][nb][2], acc[mt][nb][3]);
            *reinterpret_cast<float2*>(pp + (size_t)rr * NOUT + cc)       = v01;
            *reinterpret_cast<float2*>(pp + (size_t)(rr + 8) * NOUT + cc) = v23;
        }
    }
}

// ---------------- kernel 3: reduce partials + bias ----------------
__global__ __launch_bounds__(256)
void reduce_kernel(const float* __restrict__ bias, float* __restrict__ out) {
    int idx = blockIdx.x * 256 + threadIdx.x;     // 16384 outputs
    int n = idx & 63;
    float acc = __ldg(bias + n);
    const float* p = g_Part + idx;
    #pragma unroll 4
    for (int s = 0; s < NSPLIT; ++s)
        acc += __ldg(p + (size_t)s * (BATCH * NOUT));
    out[idx] = acc;
}

// ---------------- launch ----------------
extern "C" void kernel_launch(void* const* d_in, const int* in_sizes, int n_in,
                              void* d_out, int out_size) {
    const float* x = (const float*)d_in[0];
    const float* W = (const float*)d_in[1];
    const float* b = (const float*)d_in[2];
    float* out = (float*)d_out;
    (void)in_sizes; (void)n_in; (void)out_size;

    cudaFuncSetAttribute(gemm_tf32_kernel,
                         cudaFuncAttributeMaxDynamicSharedMemorySize, SMEM_BYTES);

    fold_w_kernel<<<16384, 256>>>(W);
    gemm_tf32_kernel<<<NSPLIT, 256, SMEM_BYTES>>>(x);
    reduce_kernel<<<64, 256>>>(b, out);
}